// round 2
// baseline (speedup 1.0000x reference)
#include <cuda_runtime.h>
#include <math_constants.h>

#define N 384
#define D 128
#define MARGIN 0.2f
#define RHO 10.0f
#define GA 4                 // anchors per block
#define NBLK (N / GA)        // 96 blocks
#define NT N                 // 384 threads = one thread per row k
#define NWARP (NT / 32)      // 12 warps

__device__ double g_num;
__device__ int    g_den;
__device__ int    g_count;   // zero-initialized; last block resets each run

__global__ void __launch_bounds__(NT, 1)
facenet_fused_kernel(const int* __restrict__ classes,
                     const float* __restrict__ emb,
                     float* __restrict__ out) {
    __shared__ float  anc[GA][D];        // anchor rows
    __shared__ float  drow[GA][N];       // dot, then distance, per anchor
    __shared__ float  sqv[N];            // squared norms of all rows
    __shared__ int    cls[N];
    __shared__ short  poslist[GA][N];
    __shared__ int    npos[GA];
    __shared__ double warpsum[NWARP];
    __shared__ bool   islast;

    const int tid  = threadIdx.x;
    const int base = blockIdx.x * GA;

    // ---- load anchors, classes, init ----
    for (int idx = tid; idx < GA * D; idx += NT)
        anc[idx >> 7][idx & (D - 1)] = emb[(base + (idx >> 7)) * D + (idx & (D - 1))];
    cls[tid] = classes[tid];
    if (tid < GA) npos[tid] = 0;
    __syncthreads();

    // ---- fused Gram row + norms: thread tid owns row k = tid ----
    {
        const int k = tid;
        const float4* rowk = reinterpret_cast<const float4*>(emb + k * D);
        const float4* a0 = reinterpret_cast<const float4*>(anc[0]);
        const float4* a1 = reinterpret_cast<const float4*>(anc[1]);
        const float4* a2 = reinterpret_cast<const float4*>(anc[2]);
        const float4* a3 = reinterpret_cast<const float4*>(anc[3]);
        float d0 = 0.f, d1 = 0.f, d2 = 0.f, d3 = 0.f, sq = 0.f;
#pragma unroll
        for (int q = 0; q < D / 4; q++) {
            float4 v = rowk[q];
            float4 w0 = a0[q], w1 = a1[q], w2 = a2[q], w3 = a3[q];
            sq = fmaf(v.x, v.x, fmaf(v.y, v.y, fmaf(v.z, v.z, fmaf(v.w, v.w, sq))));
            d0 = fmaf(v.x, w0.x, fmaf(v.y, w0.y, fmaf(v.z, w0.z, fmaf(v.w, w0.w, d0))));
            d1 = fmaf(v.x, w1.x, fmaf(v.y, w1.y, fmaf(v.z, w1.z, fmaf(v.w, w1.w, d1))));
            d2 = fmaf(v.x, w2.x, fmaf(v.y, w2.y, fmaf(v.z, w2.z, fmaf(v.w, w2.w, d2))));
            d3 = fmaf(v.x, w3.x, fmaf(v.y, w3.y, fmaf(v.z, w3.z, fmaf(v.w, w3.w, d3))));
        }
        drow[0][k] = d0; drow[1][k] = d1; drow[2][k] = d2; drow[3][k] = d3;
        sqv[k] = sq;
    }
    __syncthreads();

    // ---- dots -> clamped squared distances (in place) ----
    {
        const int k = tid;
        const float sqk = sqv[k];
#pragma unroll
        for (int g = 0; g < GA; g++) {
            float dist = sqv[base + g] + sqk - 2.0f * drow[g][k];
            drow[g][k] = fmaxf(dist, 0.0f);
        }
    }

    // ---- build positive lists ----
    {
        const int j = tid;
        const int cj = cls[j];
#pragma unroll
        for (int g = 0; g < GA; g++) {
            if (cj == cls[base + g] && j != base + g) {
                int p = atomicAdd(&npos[g], 1);
                poslist[g][p] = (short)j;
            }
        }
    }
    __syncthreads();

    if (tid == 0) {
        int dn = npos[0] + npos[1] + npos[2] + npos[3];
        if (dn > 0) atomicAdd(&g_den, dn);
    }

    // ---- triplet reductions: warp per positive pair ----
    const int warp = tid >> 5;
    const int lane = tid & 31;
    double wsum = 0.0;

#pragma unroll
    for (int g = 0; g < GA; g++) {
        const int   ci = cls[base + g];
        const int   np = npos[g];
        const float* dr = drow[g];
        for (int p = warp; p < np; p += NWARP) {
            const float dij = dr[poslist[g][p]];
            float semimax = 0.0f;
            float shmin   = CUDART_INF_F;
#pragma unroll
            for (int kk = 0; kk < N / 32; kk++) {
                const int k = kk * 32 + lane;
                float loss  = fmaxf(MARGIN - (dr[k] - dij), 0.0f);
                bool  valid = (cls[k] != ci);
                if (valid && loss > 0.0f && loss <= MARGIN)
                    semimax = fmaxf(semimax, loss);
                float sh = loss - ((valid && loss > MARGIN) ? RHO : 0.0f);
                shmin = fminf(shmin, sh);
            }
#pragma unroll
            for (int off = 16; off; off >>= 1) {
                semimax = fmaxf(semimax, __shfl_xor_sync(0xffffffffu, semimax, off));
                shmin   = fminf(shmin,   __shfl_xor_sync(0xffffffffu, shmin,   off));
            }
            float pph = (shmin < 0.0f) ? (shmin + RHO) : 0.0f;
            float ppl = semimax + ((semimax == 0.0f) ? pph : 0.0f);
            wsum += (double)ppl;   // lane-identical after reduction
        }
    }

    if (lane == 0) warpsum[warp] = wsum;
    __syncthreads();

    if (tid == 0) {
        double s = 0.0;
#pragma unroll
        for (int w = 0; w < NWARP; w++) s += warpsum[w];
        if (s != 0.0) atomicAdd(&g_num, s);
        __threadfence();
        int t = atomicAdd(&g_count, 1);
        islast = (t == NBLK - 1);
    }
    __syncthreads();

    // ---- last block finalizes and resets accumulators for next replay ----
    if (islast && tid == 0) {
        double num = atomicAdd(&g_num, 0.0);   // fenced read
        int    den = atomicAdd(&g_den, 0);
        double r = (den > 0) ? (num / fmax((double)den, 1.0)) : 0.0;
        out[0] = (float)r;
        g_num = 0.0;
        g_den = 0;
        __threadfence();
        g_count = 0;
    }
}

extern "C" void kernel_launch(void* const* d_in, const int* in_sizes, int n_in,
                              void* d_out, int out_size) {
    const int*   classes = (const int*)d_in[0];
    const float* emb     = (const float*)d_in[1];
    facenet_fused_kernel<<<NBLK, NT>>>(classes, emb, (float*)d_out);
}

// round 3
// speedup vs baseline: 1.7097x; 1.7097x over previous
#include <cuda_runtime.h>
#include <math_constants.h>

#define N 384
#define D 128
#define MARGIN 0.2f
#define RHO 10.0f
#define NBLK_B N            // triplet blocks

__device__ float  g_dist[N * N];
__device__ double g_num;
__device__ int    g_den;
__device__ int    g_count;   // zero-init; last block resets each run

// ---------------------------------------------------------------------------
// Kernel A: pairwise squared distances, tiled 32x32 Gram, norms from smem.
// grid (12,12), 256 threads.
// ---------------------------------------------------------------------------
__global__ void __launch_bounds__(256)
dist_kernel(const float* __restrict__ emb) {
    __shared__ float As[32][D];       // anchor rows (row-major, broadcast reads)
    __shared__ float Bs[D][33];       // transposed + padded
    __shared__ float sqA[32], sqB[32];

    const int bi = blockIdx.y * 32;
    const int bj = blockIdx.x * 32;
    const int tid = threadIdx.x;

    for (int idx = tid; idx < 32 * D; idx += 256) {
        int r = idx >> 7;
        int c = idx & (D - 1);
        As[r][c] = emb[(bi + r) * D + c];
        Bs[c][r] = emb[(bj + r) * D + c];
    }
    __syncthreads();

    // local squared norms (threads 0..63)
    if (tid < 32) {
        float s = 0.f;
#pragma unroll
        for (int d = 0; d < D; d++) s = fmaf(As[tid][d], As[tid][d], s);
        sqA[tid] = s;
    } else if (tid < 64) {
        const int r = tid - 32;
        float s = 0.f;
#pragma unroll
        for (int d = 0; d < D; d++) s = fmaf(Bs[d][r], Bs[d][r], s);
        sqB[r] = s;
    }
    __syncthreads();

    const int c  = tid & 31;
    const int r0 = tid >> 5;          // 0..7
    float acc[4] = {0.f, 0.f, 0.f, 0.f};
    for (int d = 0; d < D; d++) {
        float b = Bs[d][c];
#pragma unroll
        for (int q = 0; q < 4; q++)
            acc[q] = fmaf(As[r0 + 8 * q][d], b, acc[q]);
    }
#pragma unroll
    for (int q = 0; q < 4; q++) {
        const int r = r0 + 8 * q;
        float dist = sqA[r] + sqB[c] - 2.0f * acc[q];
        g_dist[(bi + r) * N + (bj + c)] = fmaxf(dist, 0.0f);
    }
}

// ---------------------------------------------------------------------------
// Kernel B: per-anchor triplet reduction (one block per anchor) + finalize.
// ---------------------------------------------------------------------------
__global__ void __launch_bounds__(256)
triplet_kernel(const int* __restrict__ classes, float* __restrict__ out) {
    __shared__ float  drow[N];
    __shared__ int    cls[N];
    __shared__ short  poslist[N];
    __shared__ int    npos;
    __shared__ double warpsum[8];
    __shared__ bool   islast;

    const int i   = blockIdx.x;
    const int tid = threadIdx.x;      // 256 threads, 8 warps
    if (tid == 0) npos = 0;

    for (int j = tid; j < N; j += 256) {
        drow[j] = g_dist[i * N + j];
        cls[j]  = classes[j];
    }
    __syncthreads();

    const int ci = cls[i];
    for (int j = tid; j < N; j += 256) {
        if (cls[j] == ci && j != i) {
            int p = atomicAdd(&npos, 1);
            poslist[p] = (short)j;
        }
    }
    __syncthreads();

    const int np = npos;
    if (tid == 0 && np > 0) atomicAdd(&g_den, np);

    const int warp = tid >> 5;
    const int lane = tid & 31;
    double wsum = 0.0;

    for (int p = warp; p < np; p += 8) {
        const float dij = drow[poslist[p]];
        float semimax = 0.0f;
        float shmin   = CUDART_INF_F;
#pragma unroll
        for (int kk = 0; kk < N / 32; kk++) {
            const int k = kk * 32 + lane;
            float loss  = fmaxf(MARGIN - (drow[k] - dij), 0.0f);
            bool  valid = (cls[k] != ci);
            if (valid && loss > 0.0f && loss <= MARGIN)
                semimax = fmaxf(semimax, loss);
            float sh = loss - ((valid && loss > MARGIN) ? RHO : 0.0f);
            shmin = fminf(shmin, sh);
        }
#pragma unroll
        for (int off = 16; off; off >>= 1) {
            semimax = fmaxf(semimax, __shfl_xor_sync(0xffffffffu, semimax, off));
            shmin   = fminf(shmin,   __shfl_xor_sync(0xffffffffu, shmin,   off));
        }
        float pph = (shmin < 0.0f) ? (shmin + RHO) : 0.0f;
        float ppl = semimax + ((semimax == 0.0f) ? pph : 0.0f);
        wsum += (double)ppl;          // lane-identical after reduction
    }

    if (lane == 0) warpsum[warp] = wsum;
    __syncthreads();

    if (tid == 0) {
        double s = 0.0;
#pragma unroll
        for (int w = 0; w < 8; w++) s += warpsum[w];
        if (s != 0.0) atomicAdd(&g_num, s);
        __threadfence();
        int t = atomicAdd(&g_count, 1);
        islast = (t == NBLK_B - 1);
    }
    __syncthreads();

    if (islast && tid == 0) {
        double num = atomicAdd(&g_num, 0.0);   // fenced read
        int    den = atomicAdd(&g_den, 0);
        double r = (den > 0) ? (num / fmax((double)den, 1.0)) : 0.0;
        out[0] = (float)r;
        g_num = 0.0;
        g_den = 0;
        __threadfence();
        g_count = 0;
    }
}

// ---------------------------------------------------------------------------
extern "C" void kernel_launch(void* const* d_in, const int* in_sizes, int n_in,
                              void* d_out, int out_size) {
    const int*   classes = (const int*)d_in[0];
    const float* emb     = (const float*)d_in[1];

    dim3 grid(N / 32, N / 32);        // 12 x 12 = 144 blocks
    dist_kernel<<<grid, 256>>>(emb);
    triplet_kernel<<<NBLK_B, 256>>>(classes, (float*)d_out);
}